// round 8
// baseline (speedup 1.0000x reference)
#include <cuda_runtime.h>
#include <cuda_bf16.h>
#include <cstdint>

#define Bb 4
#define Hh 200
#define Ww 200
#define Tt 5
#define C4 16                  // float4 per 64-channel dim
#define PIX_F4 (Tt * C4)       // 80 float4 per pixel = 1280 B contiguous
#define WT 25                  // w tiles of 8 per row
#define HT 100                 // h tile-pairs
#define BLOCKS_PER_BATCH (WT * HT)          // 2500
#define TOTAL_BLOCKS (Bb * BLOCKS_PER_BATCH) // 10000
#define ROW_BYTES (8 * PIX_F4 * 16)         // 10,240 B per 8-pixel row segment

__device__ __forceinline__ uint32_t smem_u32(const void* p) {
    uint32_t a;
    asm("{ .reg .u64 t; cvta.to.shared.u64 t, %1; cvt.u32.u64 %0, t; }" : "=r"(a) : "l"(p));
    return a;
}

__global__ __launch_bounds__(256, 4) void align_bev_tma(
    const float4* __restrict__ in,
    const float*  __restrict__ ego,
    float4* __restrict__ out)
{
    __shared__ float4 stile[2][8][PIX_F4];   // 20,480 B: [hrow][px][t*16+c4]

    // ---- block -> (b, h0, w0) ----
    int bid = blockIdx.x;
    int b   = bid / BLOCKS_PER_BATCH;
    int r   = bid - b * BLOCKS_PER_BATCH;
    int hy  = r / WT;                 // 0..99
    int wx  = r - hy * WT;            // 0..24
    int h0  = hy * 2;
    int w0  = wx * 8;

    int tid  = threadIdx.x;
    int c4   = tid & 15;
    int px   = (tid >> 4) & 7;
    int hrow = tid >> 7;              // 0/1

    int w = w0 + px;
    int h = h0 + hrow;
    int pix = (b * Hh + h) * Ww + w;

    // ---- per-pixel transform (duplicated over 16 c4 lanes; cheap) ----
    float dxn  = ego[3 * b + 0] * 0.01f;    // / (MAP_RANGE/2 = 100)
    float dyn  = ego[3 * b + 1] * 0.01f;
    float dyaw = ego[3 * b + 2];

    float s, c;
    sincosf(dyaw, &s, &c);
    float tfx = -(c * dxn + s * dyn);
    float tfy =  s * dxn - c * dyn;

    float xsv = (2.0f * (float)w + 1.0f) * (1.0f / (float)Ww) - 1.0f;
    float ysv = (2.0f * (float)h + 1.0f) * (1.0f / (float)Hh) - 1.0f;

    float gx =  c * xsv + s * ysv + tfx;
    float gy = -s * xsv + c * ysv + tfy;

    float ixv = ((gx + 1.0f) * (float)Ww - 1.0f) * 0.5f;
    float iyv = ((gy + 1.0f) * (float)Hh - 1.0f) * 0.5f;

    float ix0f = floorf(ixv);
    float iy0f = floorf(iyv);
    float wx1 = ixv - ix0f, wx0 = 1.0f - wx1;
    float wy1 = iyv - iy0f, wy0 = 1.0f - wy1;
    float ix1f = ix0f + 1.0f;
    float iy1f = iy0f + 1.0f;

    float mx0 = (ix0f >= 0.0f && ix0f <= (float)(Ww - 1)) ? 1.0f : 0.0f;
    float mx1 = (ix1f >= 0.0f && ix1f <= (float)(Ww - 1)) ? 1.0f : 0.0f;
    float my0 = (iy0f >= 0.0f && iy0f <= (float)(Hh - 1)) ? 1.0f : 0.0f;
    float my1 = (iy1f >= 0.0f && iy1f <= (float)(Hh - 1)) ? 1.0f : 0.0f;

    int x0 = (int)fminf(fmaxf(ix0f, 0.0f), (float)(Ww - 1));
    int x1 = (int)fminf(fmaxf(ix1f, 0.0f), (float)(Ww - 1));
    int y0 = (int)fminf(fmaxf(iy0f, 0.0f), (float)(Hh - 1));
    int y1 = (int)fminf(fmaxf(iy1f, 0.0f), (float)(Hh - 1));

    float w00 = wy0 * wx0 * (my0 * mx0);
    float w01 = wy0 * wx1 * (my0 * mx1);
    float w10 = wy1 * wx0 * (my1 * mx0);
    float w11 = wy1 * wx1 * (my1 * mx1);

    int baseB = b * (Hh * Ww);
    int o00 = (baseB + y0 * Ww + x0) * PIX_F4 + c4;
    int o01 = (baseB + y0 * Ww + x1) * PIX_F4 + c4;
    int o10 = (baseB + y1 * Ww + x0) * PIX_F4 + c4;
    int o11 = (baseB + y1 * Ww + x1) * PIX_F4 + c4;
    int inbase = pix * PIX_F4 + c4;

    // ---- wave A loads (t0,t1) ----
    float4 a00 = __ldg(&in[o00 +  0]);
    float4 a01 = __ldg(&in[o01 +  0]);
    float4 a10 = __ldg(&in[o10 +  0]);
    float4 a11 = __ldg(&in[o11 +  0]);
    float4 b00 = __ldg(&in[o00 + 16]);
    float4 b01 = __ldg(&in[o01 + 16]);
    float4 b10 = __ldg(&in[o10 + 16]);
    float4 b11 = __ldg(&in[o11 + 16]);
    // ---- wave B loads (t2,t3) + passthrough, issued before consuming A ----
    float4 e00 = __ldg(&in[o00 + 32]);
    float4 e01 = __ldg(&in[o01 + 32]);
    float4 e10 = __ldg(&in[o10 + 32]);
    float4 e11 = __ldg(&in[o11 + 32]);
    float4 f00 = __ldg(&in[o00 + 48]);
    float4 f01 = __ldg(&in[o01 + 48]);
    float4 f10 = __ldg(&in[o10 + 48]);
    float4 f11 = __ldg(&in[o11 + 48]);
    float4 cur = __ldcs(&in[inbase + 64]);

    float4 r0, r1, r2, r3;
    r0.x = w00*a00.x + w01*a01.x + w10*a10.x + w11*a11.x;
    r0.y = w00*a00.y + w01*a01.y + w10*a10.y + w11*a11.y;
    r0.z = w00*a00.z + w01*a01.z + w10*a10.z + w11*a11.z;
    r0.w = w00*a00.w + w01*a01.w + w10*a10.w + w11*a11.w;
    r1.x = w00*b00.x + w01*b01.x + w10*b10.x + w11*b11.x;
    r1.y = w00*b00.y + w01*b01.y + w10*b10.y + w11*b11.y;
    r1.z = w00*b00.z + w01*b01.z + w10*b10.z + w11*b11.z;
    r1.w = w00*b00.w + w01*b01.w + w10*b10.w + w11*b11.w;
    stile[hrow][px][ 0 + c4] = r0;
    stile[hrow][px][16 + c4] = r1;

    r2.x = w00*e00.x + w01*e01.x + w10*e10.x + w11*e11.x;
    r2.y = w00*e00.y + w01*e01.y + w10*e10.y + w11*e11.y;
    r2.z = w00*e00.z + w01*e01.z + w10*e10.z + w11*e11.z;
    r2.w = w00*e00.w + w01*e01.w + w10*e10.w + w11*e11.w;
    r3.x = w00*f00.x + w01*f01.x + w10*f10.x + w11*f11.x;
    r3.y = w00*f00.y + w01*f01.y + w10*f10.y + w11*f11.y;
    r3.z = w00*f00.z + w01*f01.z + w10*f10.z + w11*f11.z;
    r3.w = w00*f00.w + w01*f01.w + w10*f10.w + w11*f11.w;
    stile[hrow][px][32 + c4] = r2;
    stile[hrow][px][48 + c4] = r3;
    stile[hrow][px][64 + c4] = cur;

    __syncthreads();

    // ---- bulk store: one 10,240B contiguous segment per output row ----
    if (tid < 2) {
        asm volatile("fence.proxy.async.shared::cta;" ::: "memory");
        float4* gdst = out + ((long)(b * Hh + h0 + tid) * Ww + w0) * PIX_F4;
        uint32_t ssrc = smem_u32(&stile[tid][0][0]);
        asm volatile(
            "cp.async.bulk.global.shared::cta.bulk_group [%0], [%1], %2;"
            :: "l"(gdst), "r"(ssrc), "n"(ROW_BYTES) : "memory");
        asm volatile("cp.async.bulk.commit_group;" ::: "memory");
        asm volatile("cp.async.bulk.wait_group 0;" ::: "memory");
    }
}

extern "C" void kernel_launch(void* const* d_in, const int* in_sizes, int n_in,
                              void* d_out, int out_size)
{
    const float4* in  = (const float4*)d_in[0];   // raw_bev_cache (4,200,200,5,64) f32
    const float*  ego = (const float*)d_in[1];    // delta_ego_motion (4,3) f32
    float4* out = (float4*)d_out;

    align_bev_tma<<<TOTAL_BLOCKS, 256>>>(in, ego, out);
}

// round 9
// speedup vs baseline: 1.0041x; 1.0041x over previous
#include <cuda_runtime.h>
#include <cuda_bf16.h>

#define Bb 4
#define Hh 200
#define Ww 200
#define Tt 5
#define C4 16                 // float4 per 64-channel dim
#define PIX_F4 (Tt * C4)      // 80 float4 per (b,h,w) pixel

// Tiling identical to Round 5 (best known): block = 8(w) x 2(h) pixels x 16 c4.
#define BLOCKS_PER_BATCH 2500
#define BLOCKS_PER_ST 50
#define TOTAL_BLOCKS (Bb * BLOCKS_PER_BATCH)   // 10000

__global__ __launch_bounds__(256, 4) void align_bev_v9(
    const float4* __restrict__ in,
    const float*  __restrict__ ego,
    float4* __restrict__ out)
{
    // ---- 2D-local block decode (as R5) ----
    int bid   = blockIdx.x;
    int b     = bid / BLOCKS_PER_BATCH;
    int r     = bid - b * BLOCKS_PER_BATCH;
    int st    = r / BLOCKS_PER_ST;
    int inner = r - st * BLOCKS_PER_ST;
    int stx   = st % 5;
    int sty   = st / 5;
    int tx    = inner % 5;
    int ty    = inner / 5;
    int tile_x = stx * 5 + tx;              // 0..24
    int tile_y = sty * 10 + ty;             // 0..99

    int c4 = threadIdx.x & 15;
    int px = threadIdx.x >> 4;              // 0..15 pixel within tile
    int w  = tile_x * 8 + (px & 7);
    int h  = tile_y * 2 + (px >> 3);

    int pix = (b * Hh + h) * Ww + w;

    // ---- per-pixel transform ----
    float dxn  = ego[3 * b + 0] * 0.01f;    // / (MAP_RANGE/2 = 100)
    float dyn  = ego[3 * b + 1] * 0.01f;
    float dyaw = ego[3 * b + 2];

    float s, c;
    sincosf(dyaw, &s, &c);
    float tfx = -(c * dxn + s * dyn);
    float tfy =  s * dxn - c * dyn;

    const float invW = 1.0f / (float)Ww;
    const float invH = 1.0f / (float)Hh;
    float xsv = (2.0f * (float)w + 1.0f) * invW - 1.0f;
    float ysv = (2.0f * (float)h + 1.0f) * invH - 1.0f;

    float gx =  c * xsv + s * ysv + tfx;
    float gy = -s * xsv + c * ysv + tfy;

    float ixv = ((gx + 1.0f) * (float)Ww - 1.0f) * 0.5f;
    float iyv = ((gy + 1.0f) * (float)Hh - 1.0f) * 0.5f;

    float ix0f = floorf(ixv);
    float iy0f = floorf(iyv);
    float wx1 = ixv - ix0f, wx0 = 1.0f - wx1;
    float wy1 = iyv - iy0f, wy0 = 1.0f - wy1;
    float ix1f = ix0f + 1.0f;
    float iy1f = iy0f + 1.0f;

    float mx0 = (ix0f >= 0.0f && ix0f <= (float)(Ww - 1)) ? 1.0f : 0.0f;
    float mx1 = (ix1f >= 0.0f && ix1f <= (float)(Ww - 1)) ? 1.0f : 0.0f;
    float my0 = (iy0f >= 0.0f && iy0f <= (float)(Hh - 1)) ? 1.0f : 0.0f;
    float my1 = (iy1f >= 0.0f && iy1f <= (float)(Hh - 1)) ? 1.0f : 0.0f;

    float w00 = wy0 * wx0 * (my0 * mx0);
    float w01 = wy0 * wx1 * (my0 * mx1);
    float w10 = wy1 * wx0 * (my1 * mx0);
    float w11 = wy1 * wx1 * (my1 * mx1);

    int outbase = pix * PIX_F4 + c4;
    int tc4 = (Tt - 1) * C4;

    // passthrough always needed; issue it first so it overlaps everything
    float4 cur = __ldcs(&in[outbase + tc4]);

    if (w00 + w01 + w10 + w11 != 0.0f) {
        // ---- valid pixel: full gather + blend (R5 schedule) ----
        int x0 = (int)fminf(fmaxf(ix0f, 0.0f), (float)(Ww - 1));
        int x1 = (int)fminf(fmaxf(ix1f, 0.0f), (float)(Ww - 1));
        int y0 = (int)fminf(fmaxf(iy0f, 0.0f), (float)(Hh - 1));
        int y1 = (int)fminf(fmaxf(iy1f, 0.0f), (float)(Hh - 1));

        int baseB = b * (Hh * Ww);
        int o00 = (baseB + y0 * Ww + x0) * PIX_F4 + c4;
        int o01 = (baseB + y0 * Ww + x1) * PIX_F4 + c4;
        int o10 = (baseB + y1 * Ww + x0) * PIX_F4 + c4;
        int o11 = (baseB + y1 * Ww + x1) * PIX_F4 + c4;

        float4 a00 = __ldg(&in[o00 +  0]);
        float4 a01 = __ldg(&in[o01 +  0]);
        float4 a10 = __ldg(&in[o10 +  0]);
        float4 a11 = __ldg(&in[o11 +  0]);
        float4 b00 = __ldg(&in[o00 + 16]);
        float4 b01 = __ldg(&in[o01 + 16]);
        float4 b10 = __ldg(&in[o10 + 16]);
        float4 b11 = __ldg(&in[o11 + 16]);
        float4 e00 = __ldg(&in[o00 + 32]);
        float4 e01 = __ldg(&in[o01 + 32]);
        float4 e10 = __ldg(&in[o10 + 32]);
        float4 e11 = __ldg(&in[o11 + 32]);
        float4 f00 = __ldg(&in[o00 + 48]);
        float4 f01 = __ldg(&in[o01 + 48]);
        float4 f10 = __ldg(&in[o10 + 48]);
        float4 f11 = __ldg(&in[o11 + 48]);

        float4 r0, r1, r2, r3;
        r0.x = w00*a00.x + w01*a01.x + w10*a10.x + w11*a11.x;
        r0.y = w00*a00.y + w01*a01.y + w10*a10.y + w11*a11.y;
        r0.z = w00*a00.z + w01*a01.z + w10*a10.z + w11*a11.z;
        r0.w = w00*a00.w + w01*a01.w + w10*a10.w + w11*a11.w;
        r1.x = w00*b00.x + w01*b01.x + w10*b10.x + w11*b11.x;
        r1.y = w00*b00.y + w01*b01.y + w10*b10.y + w11*b11.y;
        r1.z = w00*b00.z + w01*b01.z + w10*b10.z + w11*b11.z;
        r1.w = w00*b00.w + w01*b01.w + w10*b10.w + w11*b11.w;
        __stcs(&out[outbase +  0], r0);
        __stcs(&out[outbase + 16], r1);

        r2.x = w00*e00.x + w01*e01.x + w10*e10.x + w11*e11.x;
        r2.y = w00*e00.y + w01*e01.y + w10*e10.y + w11*e11.y;
        r2.z = w00*e00.z + w01*e01.z + w10*e10.z + w11*e11.z;
        r2.w = w00*e00.w + w01*e01.w + w10*e10.w + w11*e11.w;
        r3.x = w00*f00.x + w01*f01.x + w10*f10.x + w11*f11.x;
        r3.y = w00*f00.y + w01*f01.y + w10*f10.y + w11*f11.y;
        r3.z = w00*f00.z + w01*f01.z + w10*f10.z + w11*f11.z;
        r3.w = w00*f00.w + w01*f01.w + w10*f10.w + w11*f11.w;
        __stcs(&out[outbase + 32], r2);
        __stcs(&out[outbase + 48], r3);
    } else {
        // ---- fully out-of-bounds: result is exactly zero for t0..t3 ----
        float4 z = make_float4(0.0f, 0.0f, 0.0f, 0.0f);
        __stcs(&out[outbase +  0], z);
        __stcs(&out[outbase + 16], z);
        __stcs(&out[outbase + 32], z);
        __stcs(&out[outbase + 48], z);
    }

    // ---- t4 passthrough ----
    __stcs(&out[outbase + tc4], cur);
}

extern "C" void kernel_launch(void* const* d_in, const int* in_sizes, int n_in,
                              void* d_out, int out_size)
{
    const float4* in  = (const float4*)d_in[0];   // raw_bev_cache (4,200,200,5,64) f32
    const float*  ego = (const float*)d_in[1];    // delta_ego_motion (4,3) f32
    float4* out = (float4*)d_out;

    align_bev_v9<<<TOTAL_BLOCKS, 256>>>(in, ego, out);
}

// round 10
// speedup vs baseline: 1.0956x; 1.0911x over previous
#include <cuda_runtime.h>
#include <cuda_bf16.h>

#define Bb 4
#define Hh 200
#define Ww 200
#define Tt 5
#define C4 16                 // float4 per 64-channel dim
#define PIX_F4 (Tt * C4)      // 80 float4 per (b,h,w) pixel

// Work decomposition identical to Round 5: tile-block = 8(w) x 2(h) pixels x 16 c4.
#define BLOCKS_PER_BATCH 2500
#define BLOCKS_PER_ST 50
#define TOTAL_TILES (Bb * BLOCKS_PER_BATCH)   // 10000 work items

// Persistent launch: exactly one wave (4 blocks/SM x 148 SMs).
#define PERSIST_BLOCKS 592

__global__ __launch_bounds__(256, 4) void align_bev_persist(
    const float4* __restrict__ in,
    const float*  __restrict__ ego,
    float4* __restrict__ out)
{
    int c4 = threadIdx.x & 15;
    int px = threadIdx.x >> 4;              // 0..15 pixel within tile
    int pw = px & 7;
    int ph = px >> 3;

    for (int bid = blockIdx.x; bid < TOTAL_TILES; bid += PERSIST_BLOCKS) {

        // ---- 2D-local tile decode (as R5) ----
        int b     = bid / BLOCKS_PER_BATCH;
        int r     = bid - b * BLOCKS_PER_BATCH;
        int st    = r / BLOCKS_PER_ST;
        int inner = r - st * BLOCKS_PER_ST;
        int stx   = st % 5;
        int sty   = st / 5;
        int tx    = inner % 5;
        int ty    = inner / 5;
        int tile_x = stx * 5 + tx;          // 0..24
        int tile_y = sty * 10 + ty;         // 0..99

        int w = tile_x * 8 + pw;
        int h = tile_y * 2 + ph;
        int pix = (b * Hh + h) * Ww + w;

        // ---- per-pixel transform ----
        float dxn  = ego[3 * b + 0] * 0.01f;    // / (MAP_RANGE/2 = 100)
        float dyn  = ego[3 * b + 1] * 0.01f;
        float dyaw = ego[3 * b + 2];

        float s, c;
        sincosf(dyaw, &s, &c);
        float tfx = -(c * dxn + s * dyn);
        float tfy =  s * dxn - c * dyn;

        float xsv = (2.0f * (float)w + 1.0f) * (1.0f / (float)Ww) - 1.0f;
        float ysv = (2.0f * (float)h + 1.0f) * (1.0f / (float)Hh) - 1.0f;

        float gx =  c * xsv + s * ysv + tfx;
        float gy = -s * xsv + c * ysv + tfy;

        float ixv = ((gx + 1.0f) * (float)Ww - 1.0f) * 0.5f;
        float iyv = ((gy + 1.0f) * (float)Hh - 1.0f) * 0.5f;

        float ix0f = floorf(ixv);
        float iy0f = floorf(iyv);
        float wx1 = ixv - ix0f, wx0 = 1.0f - wx1;
        float wy1 = iyv - iy0f, wy0 = 1.0f - wy1;
        float ix1f = ix0f + 1.0f;
        float iy1f = iy0f + 1.0f;

        float mx0 = (ix0f >= 0.0f && ix0f <= (float)(Ww - 1)) ? 1.0f : 0.0f;
        float mx1 = (ix1f >= 0.0f && ix1f <= (float)(Ww - 1)) ? 1.0f : 0.0f;
        float my0 = (iy0f >= 0.0f && iy0f <= (float)(Hh - 1)) ? 1.0f : 0.0f;
        float my1 = (iy1f >= 0.0f && iy1f <= (float)(Hh - 1)) ? 1.0f : 0.0f;

        int x0 = (int)fminf(fmaxf(ix0f, 0.0f), (float)(Ww - 1));
        int x1 = (int)fminf(fmaxf(ix1f, 0.0f), (float)(Ww - 1));
        int y0 = (int)fminf(fmaxf(iy0f, 0.0f), (float)(Hh - 1));
        int y1 = (int)fminf(fmaxf(iy1f, 0.0f), (float)(Hh - 1));

        float w00 = wy0 * wx0 * (my0 * mx0);
        float w01 = wy0 * wx1 * (my0 * mx1);
        float w10 = wy1 * wx0 * (my1 * mx0);
        float w11 = wy1 * wx1 * (my1 * mx1);

        int baseB = b * (Hh * Ww);
        int o00 = (baseB + y0 * Ww + x0) * PIX_F4 + c4;
        int o01 = (baseB + y0 * Ww + x1) * PIX_F4 + c4;
        int o10 = (baseB + y1 * Ww + x0) * PIX_F4 + c4;
        int o11 = (baseB + y1 * Ww + x1) * PIX_F4 + c4;

        int outbase = pix * PIX_F4 + c4;
        int tc4 = (Tt - 1) * C4;

        // ---- wave A loads (t0,t1) ----
        float4 a00 = __ldg(&in[o00 +  0]);
        float4 a01 = __ldg(&in[o01 +  0]);
        float4 a10 = __ldg(&in[o10 +  0]);
        float4 a11 = __ldg(&in[o11 +  0]);
        float4 b00 = __ldg(&in[o00 + 16]);
        float4 b01 = __ldg(&in[o01 + 16]);
        float4 b10 = __ldg(&in[o10 + 16]);
        float4 b11 = __ldg(&in[o11 + 16]);
        // ---- wave B loads (t2,t3) + passthrough, issued before consuming A ----
        float4 e00 = __ldg(&in[o00 + 32]);
        float4 e01 = __ldg(&in[o01 + 32]);
        float4 e10 = __ldg(&in[o10 + 32]);
        float4 e11 = __ldg(&in[o11 + 32]);
        float4 f00 = __ldg(&in[o00 + 48]);
        float4 f01 = __ldg(&in[o01 + 48]);
        float4 f10 = __ldg(&in[o10 + 48]);
        float4 f11 = __ldg(&in[o11 + 48]);
        float4 cur = __ldcs(&in[outbase + tc4]);

        // ---- blend + store wave A ----
        float4 r0, r1;
        r0.x = w00*a00.x + w01*a01.x + w10*a10.x + w11*a11.x;
        r0.y = w00*a00.y + w01*a01.y + w10*a10.y + w11*a11.y;
        r0.z = w00*a00.z + w01*a01.z + w10*a10.z + w11*a11.z;
        r0.w = w00*a00.w + w01*a01.w + w10*a10.w + w11*a11.w;
        r1.x = w00*b00.x + w01*b01.x + w10*b10.x + w11*b11.x;
        r1.y = w00*b00.y + w01*b01.y + w10*b10.y + w11*b11.y;
        r1.z = w00*b00.z + w01*b01.z + w10*b10.z + w11*b11.z;
        r1.w = w00*b00.w + w01*b01.w + w10*b10.w + w11*b11.w;
        __stcs(&out[outbase +  0], r0);
        __stcs(&out[outbase + 16], r1);

        // ---- blend + store wave B ----
        float4 r2, r3;
        r2.x = w00*e00.x + w01*e01.x + w10*e10.x + w11*e11.x;
        r2.y = w00*e00.y + w01*e01.y + w10*e10.y + w11*e11.y;
        r2.z = w00*e00.z + w01*e01.z + w10*e10.z + w11*e11.z;
        r2.w = w00*e00.w + w01*e01.w + w10*e10.w + w11*e11.w;
        r3.x = w00*f00.x + w01*f01.x + w10*f10.x + w11*f11.x;
        r3.y = w00*f00.y + w01*f01.y + w10*f10.y + w11*f11.y;
        r3.z = w00*f00.z + w01*f01.z + w10*f10.z + w11*f11.z;
        r3.w = w00*f00.w + w01*f01.w + w10*f10.w + w11*f11.w;
        __stcs(&out[outbase + 32], r2);
        __stcs(&out[outbase + 48], r3);

        // ---- passthrough ----
        __stcs(&out[outbase + tc4], cur);
    }
}

extern "C" void kernel_launch(void* const* d_in, const int* in_sizes, int n_in,
                              void* d_out, int out_size)
{
    const float4* in  = (const float4*)d_in[0];   // raw_bev_cache (4,200,200,5,64) f32
    const float*  ego = (const float*)d_in[1];    // delta_ego_motion (4,3) f32
    float4* out = (float4*)d_out;

    align_bev_persist<<<PERSIST_BLOCKS, 256>>>(in, ego, out);
}